// round 6
// baseline (speedup 1.0000x reference)
#include <cuda_runtime.h>
#include <cstdint>

// ---------------- problem constants ----------------
#define IMG      224
#define P        (IMG*IMG)          // 50176
#define NB       64
#define NR       16
#define TD       256
#define OD       192

// ---------------- tiling ----------------
#define RING_CAP 5120
#define KCHUNK   288                   // pixels per block -> ~145 active blocks (1 wave)
#define KT       16                    // K sub-tile (pipeline stage)
#define UPR      ((RING_CAP + KCHUNK - 1) / KCHUNK)   // 18
#define MAXU     (NR * UPR)            // 288
#define BM       64
#define BN       256
#define SWP      260                   // sW row pitch (floats)
#define SXP      68                    // sX row pitch (floats)

typedef unsigned long long ull;

// ---------------- device scratch ----------------
__device__ int   g_ring_idx[NR][RING_CAP];
__device__ int   g_ring_count[NR];
__device__ float g_part[(size_t)MAXU * BM * BN];   // 18.9 MB partials
__device__ float g_tokens[NB * NR * TD];

// ---------------- helpers ----------------
__device__ __forceinline__ ull dup2(float v) {
    ull r; asm("mov.b64 %0, {%1, %1};" : "=l"(r) : "f"(v)); return r;
}
__device__ __forceinline__ float2 unpack2(ull v) {
    float2 f; asm("mov.b64 {%0, %1}, %2;" : "=f"(f.x), "=f"(f.y) : "l"(v)); return f;
}
__device__ __forceinline__ void fma2(ull& acc, ull a, ull b) {
    asm("fma.rn.f32x2 %0, %1, %2, %0;" : "+l"(acc) : "l"(a), "l"(b));
}
__device__ __forceinline__ void cpasync4(uint32_t saddr, const void* gaddr) {
    asm volatile("cp.async.ca.shared.global [%0], [%1], 4;" :: "r"(saddr), "l"(gaddr));
}
__device__ __forceinline__ void cpasync_commit() {
    asm volatile("cp.async.commit_group;");
}
__device__ __forceinline__ void cpasync_wait_all() {
    asm volatile("cp.async.wait_group 0;");
}

// ---------------- K1: per-ring stable pixel lists (pipelined) ----------------
__global__ __launch_bounds__(1024) void k_build_rings(const float* __restrict__ masks) {
    const int c = blockIdx.x;
    const float* m = masks + (size_t)c * P;
    __shared__ int s_cnt[32];
    __shared__ int s_off[32];
    const int lane = threadIdx.x & 31;
    const int warp = threadIdx.x >> 5;
    const int base = warp * (P / 32);       // 1568 contiguous pixels per warp

    int cnt = 0;
#pragma unroll 7
    for (int it = 0; it < 49; it++) {
        cnt += (m[base + it * 32 + lane] != 0.0f) ? 1 : 0;
    }
#pragma unroll
    for (int d = 16; d >= 1; d >>= 1)
        cnt += __shfl_xor_sync(0xFFFFFFFFu, cnt, d);
    if (lane == 0) s_cnt[warp] = cnt;
    __syncthreads();
    if (warp == 0) {
        int v = s_cnt[lane];
        int sum = v;
#pragma unroll
        for (int d = 1; d < 32; d <<= 1) {
            int o = __shfl_up_sync(0xFFFFFFFFu, sum, d);
            if (lane >= d) sum += o;
        }
        s_off[lane] = sum - v;
        if (lane == 31) g_ring_count[c] = (sum < RING_CAP) ? sum : RING_CAP;
    }
    __syncthreads();

    int off = s_off[warp];
    const unsigned lmask = (1u << lane) - 1u;
    for (int bt = 0; bt < 7; bt++) {
        float v[7];
#pragma unroll
        for (int i = 0; i < 7; i++)
            v[i] = m[base + (bt * 7 + i) * 32 + lane];
#pragma unroll
        for (int i = 0; i < 7; i++) {
            bool in = (v[i] != 0.0f);
            unsigned bl = __ballot_sync(0xFFFFFFFFu, in);
            if (in) {
                int rank = off + __popc(bl & lmask);
                if (rank < RING_CAP) g_ring_idx[c][rank] = base + (bt * 7 + i) * 32 + lane;
            }
            off += __popc(bl);
        }
    }
}

// ---------------- K2: segmented GEMM, 512 threads, f32x2 ----------------
// grid (UPR, NR). BM=64 x BN=256 per block, KCHUNK=288 pixels, KT=16 stages.
// 16 warps: bw=w&1 (32 b), dw=w>>1 (32 d). Lane: 4b x 8d.
__global__ __launch_bounds__(512, 1) void k_gemm(const float* __restrict__ x,
                                                 const float* __restrict__ W) {
    __shared__ __align__(16) float sW[2][KT][SWP];   // 33.3 KB
    __shared__ __align__(16) float sX[2][KT][SXP];   //  8.7 KB

    const int c  = blockIdx.y;
    const int nc = g_ring_count[c];
    const int s0 = blockIdx.x * KCHUNK;
    if (s0 >= nc) return;
    const int send = (s0 + KCHUNK < nc) ? (s0 + KCHUNK) : nc;
    const int nT   = (send - s0 + KT - 1) / KT;

    const int t    = threadIdx.x;
    const int lane = t & 31;
    const int w    = t >> 5;

    // loader roles
    const int j  = t & 15;          // pixel within K-tile
    const int dg = t >> 4;          // 0..31 (8 d's each)
    const int bg = t >> 4;          // 0..31 (2 b's each)

    const uint32_t swbase = (uint32_t)__cvta_generic_to_shared(&sW[0][0][0]);
    const int* ridx = g_ring_idx[c];

    float rx0, rx1;
    auto loadX = [&](int tl) {
        int jj = s0 + tl * KT + j;
        int p  = (jj < send) ? ridx[jj] : -1;
        if (p >= 0) {
            rx0 = __ldg(&x[(size_t)(bg * 2 + 0) * P + p]);
            rx1 = __ldg(&x[(size_t)(bg * 2 + 1) * P + p]);
        } else {
            rx0 = 0.0f; rx1 = 0.0f;
        }
    };
    auto stsX = [&](int buf) {
        *(float2*)&sX[buf][j][bg * 2] = make_float2(rx0, rx1);
    };
    auto issueW = [&](int buf, int tl) {
        int jj = s0 + tl * KT + j;
        int p  = (jj < send) ? ridx[jj] : 0;
        if (p < 0) p = 0;
        const float* g = &W[(size_t)(dg * 8) * P + p];
        uint32_t d = swbase + (uint32_t)((buf * KT + j) * SWP + dg * 8) * 4u;
#pragma unroll
        for (int i = 0; i < 8; i++) {
            cpasync4(d, g);
            g += (size_t)P;
            d += 4;
        }
    };

    // compute mapping
    const int bw = w & 1, dw = w >> 1;
    const int lb = lane >> 2, ld = lane & 3;
    const int b_base = bw * 32 + lb * 4;
    const int d_base = dw * 32 + ld * 8;

    ull acc[4][4];
#pragma unroll
    for (int i = 0; i < 4; i++)
#pragma unroll
        for (int jj2 = 0; jj2 < 4; jj2++) acc[i][jj2] = 0ull;

    auto compute = [&](int buf) {
#pragma unroll
        for (int p = 0; p < KT; p++) {
            float4 xv = *(const float4*)&sX[buf][p][b_base];
            ull xr[4];
            xr[0] = dup2(xv.x); xr[1] = dup2(xv.y);
            xr[2] = dup2(xv.z); xr[3] = dup2(xv.w);
            const ulonglong2* wr2 = (const ulonglong2*)&sW[buf][p][d_base];
            ulonglong2 wv0 = wr2[0], wv1 = wr2[1];
            ull wr[4] = {wv0.x, wv0.y, wv1.x, wv1.y};
#pragma unroll
            for (int bi = 0; bi < 4; bi++)
#pragma unroll
                for (int dj = 0; dj < 4; dj++)
                    fma2(acc[bi][dj], xr[bi], wr[dj]);
        }
    };

    // ---- software pipeline ----
    loadX(0);
    issueW(0, 0);
    cpasync_commit();
    stsX(0);
    cpasync_wait_all();
    __syncthreads();

    for (int tl = 0; tl < nT; tl++) {
        const int cur = tl & 1, nxt = cur ^ 1;
        const bool more = (tl + 1 < nT);
        if (more) {
            loadX(tl + 1);
            issueW(nxt, tl + 1);
            cpasync_commit();
        }
        compute(cur);
        if (more) {
            stsX(nxt);
            cpasync_wait_all();
        }
        __syncthreads();
    }

    // ---- flush partials ----
    const int u = c * UPR + blockIdx.x;
    float* outp = g_part + (size_t)u * BM * BN;
#pragma unroll
    for (int bi = 0; bi < 4; bi++) {
        int b = b_base + bi;
        float2 f0 = unpack2(acc[bi][0]);
        float2 f1 = unpack2(acc[bi][1]);
        float2 f2 = unpack2(acc[bi][2]);
        float2 f3 = unpack2(acc[bi][3]);
        float4* dst = (float4*)&outp[(size_t)b * BN + d_base];
        dst[0] = make_float4(f0.x, f0.y, f1.x, f1.y);
        dst[1] = make_float4(f2.x, f2.y, f3.x, f3.y);
    }
}

// ---------------- K3: reduce partials -> tokens ----------------
__global__ __launch_bounds__(256) void k_reduce() {
    int i = blockIdx.x * 256 + threadIdx.x;           // 65536 threads, float4 each
    int d4   = i & 63;
    int ring = (i >> 6) & 15;
    int b    = i >> 10;
    int ua = (g_ring_count[ring] + KCHUNK - 1) / KCHUNK;
    const float4* base = (const float4*)g_part;
    size_t idx = (size_t)(ring * UPR) * (BM * BN / 4) + (size_t)b * (BN / 4) + d4;
    float4 s = make_float4(0.f, 0.f, 0.f, 0.f);
    for (int u = 0; u < ua; u++) {
        float4 v = base[idx + (size_t)u * (BM * BN / 4)];
        s.x += v.x; s.y += v.y; s.z += v.z; s.w += v.w;
    }
    ((float4*)g_tokens)[(size_t)b * (NR * TD / 4) + ring * (TD / 4) + d4] = s;
}

// ---------------- K4: fc  out[m][o] = tokens[m,:] @ fc_w[o,:] + b --------------
// grid (64, 6), 128 threads. Tile 16m x 32n; thread tile 2m x 2n scalar.
__global__ __launch_bounds__(128) void k_fc(const float* __restrict__ fcw,
                                            const float* __restrict__ fcb,
                                            float* __restrict__ out) {
    __shared__ __align__(16) float sT[16][68];    // [m][k] chunk
    __shared__ __align__(16) float sF[64][36];    // [k][n] chunk (transposed)
    const int m0 = blockIdx.x * 16;
    const int n0 = blockIdx.y * 32;
    const int t  = threadIdx.x;

    const int tm2 = (t >> 4) * 2;        // 2 m rows (0..14)
    const int n2  = (t & 15) * 2;        // 2 n cols (0..30)

    float a00 = 0.f, a01 = 0.f, a10 = 0.f, a11 = 0.f;

    for (int k0 = 0; k0 < TD; k0 += 64) {
        // tokens tile: 16 m x 64 k
        {
            int r  = t >> 3;             // 16 rows, 8 threads each
            int kk = (t & 7) * 8;
            const float4* src = (const float4*)&g_tokens[(size_t)(m0 + r) * TD + k0 + kk];
            float4 va = src[0], vb = src[1];
            *(float4*)&sT[r][kk]     = va;
            *(float4*)&sT[r][kk + 4] = vb;
        }
        // fcw tile transposed: 32 n rows x 64 k -> sF[k][n]
        {
            int r  = t >> 2;             // 32 rows, 4 threads each
            int kk = (t & 3) * 16;
            const float4* src = (const float4*)&fcw[(size_t)(n0 + r) * TD + k0 + kk];
#pragma unroll
            for (int q = 0; q < 4; q++) {
                float4 v = src[q];
                sF[kk + q * 4 + 0][r] = v.x;
                sF[kk + q * 4 + 1][r] = v.y;
                sF[kk + q * 4 + 2][r] = v.z;
                sF[kk + q * 4 + 3][r] = v.w;
            }
        }
        __syncthreads();
#pragma unroll 16
        for (int k = 0; k < 64; k++) {
            float x0 = sT[tm2][k];
            float x1 = sT[tm2 + 1][k];
            float2 wv = *(const float2*)&sF[k][n2];
            a00 += x0 * wv.x;
            a01 += x0 * wv.y;
            a10 += x1 * wv.x;
            a11 += x1 * wv.y;
        }
        __syncthreads();
    }

    float b0 = fcb[n0 + n2], b1 = fcb[n0 + n2 + 1];
    *(float2*)&out[(size_t)(m0 + tm2) * OD + n0 + n2]     = make_float2(a00 + b0, a01 + b1);
    *(float2*)&out[(size_t)(m0 + tm2 + 1) * OD + n0 + n2] = make_float2(a10 + b0, a11 + b1);
}

// ---------------- launch ----------------
extern "C" void kernel_launch(void* const* d_in, const int* in_sizes, int n_in,
                              void* d_out, int out_size) {
    const float *x = nullptr, *tw = nullptr, *fcw = nullptr, *fcb = nullptr,
                *masks = nullptr;
    for (int i = 0; i < n_in; i++) {
        switch (in_sizes[i]) {
            case NB * P:  x     = (const float*)d_in[i]; break;
            case TD * P:  tw    = (const float*)d_in[i]; break;
            case OD * TD: fcw   = (const float*)d_in[i]; break;
            case OD:      fcb   = (const float*)d_in[i]; break;
            case NR * P:  masks = (const float*)d_in[i]; break;
            default: break;
        }
    }
    if (!x)     x     = (const float*)d_in[0];
    if (!tw)    tw    = (const float*)d_in[1];
    if (!fcw)   fcw   = (const float*)d_in[2];
    if (!fcb)   fcb   = (const float*)d_in[3];
    if (!masks) masks = (const float*)d_in[4];
    float* out = (float*)d_out;

    k_build_rings<<<NR, 1024>>>(masks);
    k_gemm<<<dim3(UPR, NR), 512>>>(x, tw);
    k_reduce<<<256, 256>>>();
    k_fc<<<dim3(NB * NR / 16, OD / 32), 128>>>(fcw, fcb, out);
}

// round 7
// speedup vs baseline: 1.1115x; 1.1115x over previous
#include <cuda_runtime.h>
#include <cstdint>

// ---------------- problem constants ----------------
#define IMG      224
#define P        (IMG*IMG)          // 50176
#define NB       64
#define NR       16
#define TD       256
#define OD       192

// ---------------- tiling ----------------
#define RING_CAP 5120
#define KCHUNK   160                   // pixels per block -> ~252 active blocks (1 wave @2/SM)
#define KT       16                    // K sub-tile (pipeline stage)
#define UPR      (RING_CAP / KCHUNK)   // 32
#define MAXU     (NR * UPR)            // 512
#define BM       64
#define BN       256
#define SWP      260                   // sW row pitch (floats)
#define SXP      68                    // sX row pitch (floats)

typedef unsigned long long ull;

// ---------------- device scratch ----------------
__device__ int   g_ring_idx[NR][RING_CAP];
__device__ int   g_ring_count[NR];
__device__ float g_part[(size_t)MAXU * BM * BN];
__device__ float g_tokens[NB * NR * TD];
__device__ float g_fcpart[4][NB * NR][OD];

// ---------------- helpers ----------------
__device__ __forceinline__ ull dup2(float v) {
    ull r; asm("mov.b64 %0, {%1, %1};" : "=l"(r) : "f"(v)); return r;
}
__device__ __forceinline__ float2 unpack2(ull v) {
    float2 f; asm("mov.b64 {%0, %1}, %2;" : "=f"(f.x), "=f"(f.y) : "l"(v)); return f;
}
__device__ __forceinline__ void fma2(ull& acc, ull a, ull b) {
    asm("fma.rn.f32x2 %0, %1, %2, %0;" : "+l"(acc) : "l"(a), "l"(b));
}
__device__ __forceinline__ void cpasync4(uint32_t saddr, const void* gaddr) {
    asm volatile("cp.async.ca.shared.global [%0], [%1], 4;" :: "r"(saddr), "l"(gaddr));
}
__device__ __forceinline__ void cpasync_commit() {
    asm volatile("cp.async.commit_group;");
}
__device__ __forceinline__ void cpasync_wait_all() {
    asm volatile("cp.async.wait_group 0;");
}

// ---------------- K1: per-ring stable pixel lists (pipelined) ----------------
__global__ __launch_bounds__(1024) void k_build_rings(const float* __restrict__ masks) {
    const int c = blockIdx.x;
    const float* m = masks + (size_t)c * P;
    __shared__ int s_cnt[32];
    __shared__ int s_off[32];
    const int lane = threadIdx.x & 31;
    const int warp = threadIdx.x >> 5;
    const int base = warp * (P / 32);       // 1568 contiguous pixels per warp

    int cnt = 0;
#pragma unroll 7
    for (int it = 0; it < 49; it++) {
        cnt += (m[base + it * 32 + lane] != 0.0f) ? 1 : 0;
    }
#pragma unroll
    for (int d = 16; d >= 1; d >>= 1)
        cnt += __shfl_xor_sync(0xFFFFFFFFu, cnt, d);
    if (lane == 0) s_cnt[warp] = cnt;
    __syncthreads();
    if (warp == 0) {
        int v = s_cnt[lane];
        int sum = v;
#pragma unroll
        for (int d = 1; d < 32; d <<= 1) {
            int o = __shfl_up_sync(0xFFFFFFFFu, sum, d);
            if (lane >= d) sum += o;
        }
        s_off[lane] = sum - v;
        if (lane == 31) g_ring_count[c] = (sum < RING_CAP) ? sum : RING_CAP;
    }
    __syncthreads();

    int off = s_off[warp];
    const unsigned lmask = (1u << lane) - 1u;
    for (int bt = 0; bt < 7; bt++) {
        float v[7];
#pragma unroll
        for (int i = 0; i < 7; i++)
            v[i] = m[base + (bt * 7 + i) * 32 + lane];
#pragma unroll
        for (int i = 0; i < 7; i++) {
            bool in = (v[i] != 0.0f);
            unsigned bl = __ballot_sync(0xFFFFFFFFu, in);
            if (in) {
                int rank = off + __popc(bl & lmask);
                if (rank < RING_CAP) g_ring_idx[c][rank] = base + (bt * 7 + i) * 32 + lane;
            }
            off += __popc(bl);
        }
    }
}

// ---------------- K2: segmented GEMM, 256 threads, 2 blocks/SM ----------------
__global__ __launch_bounds__(256, 2) void k_gemm(const float* __restrict__ x,
                                                 const float* __restrict__ W) {
    __shared__ __align__(16) float sW[2][KT][SWP];   // 33.3 KB
    __shared__ __align__(16) float sX[2][KT][SXP];   //  8.7 KB

    const int c  = blockIdx.y;
    const int nc = g_ring_count[c];
    const int s0 = blockIdx.x * KCHUNK;
    if (s0 >= nc) return;
    const int send = (s0 + KCHUNK < nc) ? (s0 + KCHUNK) : nc;
    const int nT   = (send - s0 + KT - 1) / KT;

    const int t    = threadIdx.x;
    const int lane = t & 31;
    const int w    = t >> 5;

    const int j  = t & 15;          // pixel within K-tile
    const int dg = t >> 4;          // 0..15 (16 d's each)
    const int bg = t >> 4;          // 0..15 (4 b's each)

    const uint32_t swbase = (uint32_t)__cvta_generic_to_shared(&sW[0][0][0]);
    const int* ridx = g_ring_idx[c];

    float rx[4];
    auto loadX = [&](int tl) {
        int jj = s0 + tl * KT + j;
        int p  = (jj < send) ? ridx[jj] : -1;
        if (p >= 0) {
#pragma unroll
            for (int i = 0; i < 4; i++)
                rx[i] = __ldg(&x[(size_t)(bg * 4 + i) * P + p]);
        } else {
#pragma unroll
            for (int i = 0; i < 4; i++) rx[i] = 0.0f;
        }
    };
    auto stsX = [&](int buf) {
        float4* dst = (float4*)&sX[buf][j][bg * 4];
        *dst = make_float4(rx[0], rx[1], rx[2], rx[3]);
    };
    auto issueW = [&](int buf, int tl) {
        int jj = s0 + tl * KT + j;
        int p  = (jj < send) ? ridx[jj] : 0;
        if (p < 0) p = 0;
        const float* g = &W[(size_t)(dg * 16) * P + p];
        uint32_t d = swbase + (uint32_t)((buf * KT + j) * SWP + dg * 16) * 4u;
#pragma unroll
        for (int i = 0; i < 16; i++) {
            cpasync4(d, g);
            g += (size_t)P;
            d += 4;
        }
    };

    // compute mapping: warp -> (b half, d quarter); lane -> 8b x 8d tile
    const int bw = w & 1, dw = w >> 1;
    const int lb = lane & 3, ld = lane >> 2;
    const int b_base = bw * 32 + lb * 8;
    const int d_base = dw * 64 + ld * 8;

    ull acc[8][4];
#pragma unroll
    for (int i = 0; i < 8; i++)
#pragma unroll
        for (int jj2 = 0; jj2 < 4; jj2++) acc[i][jj2] = 0ull;

    auto compute = [&](int buf) {
#pragma unroll
        for (int p = 0; p < KT; p++) {
            const float4* xr4 = (const float4*)&sX[buf][p][b_base];
            float4 xa = xr4[0], xb2 = xr4[1];
            ull xr[8];
            xr[0] = dup2(xa.x); xr[1] = dup2(xa.y);
            xr[2] = dup2(xa.z); xr[3] = dup2(xa.w);
            xr[4] = dup2(xb2.x); xr[5] = dup2(xb2.y);
            xr[6] = dup2(xb2.z); xr[7] = dup2(xb2.w);
            const ulonglong2* wr2 = (const ulonglong2*)&sW[buf][p][d_base];
            ulonglong2 wv0 = wr2[0], wv1 = wr2[1];
            ull wr[4] = {wv0.x, wv0.y, wv1.x, wv1.y};
#pragma unroll
            for (int bi = 0; bi < 8; bi++)
#pragma unroll
                for (int dj = 0; dj < 4; dj++)
                    fma2(acc[bi][dj], xr[bi], wr[dj]);
        }
    };

    loadX(0);
    issueW(0, 0);
    cpasync_commit();
    stsX(0);
    cpasync_wait_all();
    __syncthreads();

    for (int tl = 0; tl < nT; tl++) {
        const int cur = tl & 1, nxt = cur ^ 1;
        const bool more = (tl + 1 < nT);
        if (more) {
            loadX(tl + 1);
            issueW(nxt, tl + 1);
            cpasync_commit();
        }
        compute(cur);
        if (more) {
            stsX(nxt);
            cpasync_wait_all();
        }
        __syncthreads();
    }

    const int u = c * UPR + blockIdx.x;
    float* outp = g_part + (size_t)u * BM * BN;
#pragma unroll
    for (int bi = 0; bi < 8; bi++) {
        int b = b_base + bi;
        float2 f0 = unpack2(acc[bi][0]);
        float2 f1 = unpack2(acc[bi][1]);
        float2 f2 = unpack2(acc[bi][2]);
        float2 f3 = unpack2(acc[bi][3]);
        float4* dst = (float4*)&outp[(size_t)b * BN + d_base];
        dst[0] = make_float4(f0.x, f0.y, f1.x, f1.y);
        dst[1] = make_float4(f2.x, f2.y, f3.x, f3.y);
    }
}

// ---------------- K3: reduce partials -> tokens ----------------
__global__ __launch_bounds__(256) void k_reduce() {
    int i = blockIdx.x * 256 + threadIdx.x;           // 65536 threads, float4 each
    int d4   = i & 63;
    int ring = (i >> 6) & 15;
    int b    = i >> 10;
    int ua = (g_ring_count[ring] + KCHUNK - 1) / KCHUNK;
    const float4* base = (const float4*)g_part;
    size_t idx = (size_t)(ring * UPR) * (BM * BN / 4) + (size_t)b * (BN / 4) + d4;
    float4 s = make_float4(0.f, 0.f, 0.f, 0.f);
    for (int u = 0; u < ua; u++) {
        float4 v = base[idx + (size_t)u * (BM * BN / 4)];
        s.x += v.x; s.y += v.y; s.z += v.z; s.w += v.w;
    }
    ((float4*)g_tokens)[(size_t)b * (NR * TD / 4) + ring * (TD / 4) + d4] = s;
}

// ---------------- K4: fc main  (split-K) ----------------
// grid (16, 6, 4): 64m x 32n x 64k per block, 128 threads, thread tile 4m x 4n.
__global__ __launch_bounds__(128) void k_fc_main(const float* __restrict__ fcw) {
    __shared__ __align__(16) float sT[64][68];    // [m][k]
    __shared__ __align__(16) float sF[64][36];    // [k][n]
    const int m0 = blockIdx.x * 64;
    const int n0 = blockIdx.y * 32;
    const int k0 = blockIdx.z * 64;
    const int t  = threadIdx.x;

    // load tokens tile: 64 m x 64 k (2 threads per row, 32 floats each)
    {
        int r  = t >> 1;
        int kk = (t & 1) * 32;
        const float4* src = (const float4*)&g_tokens[(size_t)(m0 + r) * TD + k0 + kk];
        float4* dst = (float4*)&sT[r][kk];
#pragma unroll
        for (int q = 0; q < 8; q++) dst[q] = src[q];
    }
    // load fcw tile transposed: 32 n rows x 64 k -> sF[k][n]
    {
        int r  = t >> 2;
        int kk = (t & 3) * 16;
        const float4* src = (const float4*)&fcw[(size_t)(n0 + r) * TD + k0 + kk];
#pragma unroll
        for (int q = 0; q < 4; q++) {
            float4 v = src[q];
            sF[kk + q * 4 + 0][r] = v.x;
            sF[kk + q * 4 + 1][r] = v.y;
            sF[kk + q * 4 + 2][r] = v.z;
            sF[kk + q * 4 + 3][r] = v.w;
        }
    }
    __syncthreads();

    const int tm = (t >> 3) * 4;        // 16 m-groups
    const int tn = (t & 7) * 4;         // 8 n-groups

    ull acc[4][2];
#pragma unroll
    for (int i = 0; i < 4; i++) { acc[i][0] = 0ull; acc[i][1] = 0ull; }

#pragma unroll 8
    for (int k = 0; k < 64; k++) {
        ulonglong2 wv = *(const ulonglong2*)&sF[k][tn];
#pragma unroll
        for (int i = 0; i < 4; i++) {
            ull xv = dup2(sT[tm + i][k]);
            fma2(acc[i][0], xv, wv.x);
            fma2(acc[i][1], xv, wv.y);
        }
    }

    float* outp = &g_fcpart[blockIdx.z][0][0];
#pragma unroll
    for (int i = 0; i < 4; i++) {
        float2 a0 = unpack2(acc[i][0]);
        float2 a1 = unpack2(acc[i][1]);
        *(float4*)&outp[(size_t)(m0 + tm + i) * OD + n0 + tn] =
            make_float4(a0.x, a0.y, a1.x, a1.y);
    }
}

// ---------------- K5: fc combine + bias ----------------
__global__ __launch_bounds__(256) void k_fc_combine(const float* __restrict__ fcb,
                                                    float* __restrict__ out) {
    int i = blockIdx.x * 256 + threadIdx.x;     // float4 index, 49152 total
    if (i >= NB * NR * OD / 4) return;
    const float4* p0 = (const float4*)&g_fcpart[0][0][0];
    const float4* p1 = (const float4*)&g_fcpart[1][0][0];
    const float4* p2 = (const float4*)&g_fcpart[2][0][0];
    const float4* p3 = (const float4*)&g_fcpart[3][0][0];
    float4 a = p0[i], b = p1[i], c = p2[i], d = p3[i];
    int o4 = i % (OD / 4);
    float4 bias = ((const float4*)fcb)[o4];
    float4 r;
    r.x = a.x + b.x + c.x + d.x + bias.x;
    r.y = a.y + b.y + c.y + d.y + bias.y;
    r.z = a.z + b.z + c.z + d.z + bias.z;
    r.w = a.w + b.w + c.w + d.w + bias.w;
    ((float4*)out)[i] = r;
}

// ---------------- launch ----------------
extern "C" void kernel_launch(void* const* d_in, const int* in_sizes, int n_in,
                              void* d_out, int out_size) {
    const float *x = nullptr, *tw = nullptr, *fcw = nullptr, *fcb = nullptr,
                *masks = nullptr;
    for (int i = 0; i < n_in; i++) {
        switch (in_sizes[i]) {
            case NB * P:  x     = (const float*)d_in[i]; break;
            case TD * P:  tw    = (const float*)d_in[i]; break;
            case OD * TD: fcw   = (const float*)d_in[i]; break;
            case OD:      fcb   = (const float*)d_in[i]; break;
            case NR * P:  masks = (const float*)d_in[i]; break;
            default: break;
        }
    }
    if (!x)     x     = (const float*)d_in[0];
    if (!tw)    tw    = (const float*)d_in[1];
    if (!fcw)   fcw   = (const float*)d_in[2];
    if (!fcb)   fcb   = (const float*)d_in[3];
    if (!masks) masks = (const float*)d_in[4];
    float* out = (float*)d_out;

    k_build_rings<<<NR, 1024>>>(masks);
    k_gemm<<<dim3(UPR, NR), 256>>>(x, tw);
    k_reduce<<<256, 256>>>();
    k_fc_main<<<dim3(16, 6, 4), 128>>>(fcw);
    k_fc_combine<<<(NB * NR * OD / 4 + 255) / 256, 256>>>(fcb, out);
}